// round 2
// baseline (speedup 1.0000x reference)
#include <cuda_runtime.h>
#include <cuda_bf16.h>
#include <cstdint>
#include <math.h>

// Problem: B=4096, IN=784, H=256, OUT=10, TOL=1e-3, MAX_ITERS=200
#define NB 4096
#define NIN 784
#define NH 256
#define NOUT 10
#define TOLV 1e-3f
#define MAXIT 200
#define ROWS_PER_CTA 32
#define NCTA (NB / ROWS_PER_CTA)   // 128 CTAs <= 148 SMs -> all co-resident

// ---------------- scratch (no dynamic allocation allowed) ----------------
__device__ float g_Wq4[NH * NH];          // Wq packed as float4 tiles: [(k>>2)][h][k&3]
__device__ float g_bq[NH];
__device__ float g_ab[2];                 // alpha, beta
__device__ float g_Wip4[NIN * NH];        // W_ip^T packed same way: [(k>>2)][h][k&3], 196*1024
__device__ float g_c[NB * NH];            // bq + x@W_ip^T + b_ip
__device__ unsigned g_bar[256];           // per-iteration barrier slots (zeroed each launch)

// ---------------- K0: quantize W_raw/b_raw, alpha/beta, zero barriers ----------------
__global__ void k_setup(const float* __restrict__ W_raw, const float* __restrict__ b_raw,
                        const float* __restrict__ a_raw, const float* __restrict__ be_raw) {
    int t = threadIdx.x;
    if (blockIdx.x < NH) {
        int hh = blockIdx.x;
        float w = W_raw[hh * NH + t];
        float q = rintf(tanhf(w) * 255.0f);          // round-half-even, matches jnp.round
        q = fminf(fmaxf(q, -256.0f), 255.0f);
        g_Wq4[(t >> 2) * (NH * 4) + hh * 4 + (t & 3)] = q / 255.0f;
    } else {
        float b = b_raw[t];
        float q = rintf(tanhf(b) * 255.0f);
        q = fminf(fmaxf(q, -256.0f), 255.0f);
        g_bq[t] = q / 255.0f;
        g_bar[t] = 0u;
        if (t == 0) {
            g_ab[0] = 1.0f / (1.0f + expf(-a_raw[0]));
            g_ab[1] = 1.0f / (1.0f + expf(-be_raw[0]));
        }
    }
}

// ---------------- K1: repack W_ip[h][k] -> Wip4[(k>>2)][h][k&3] ----------------
__global__ void k_packWip(const float* __restrict__ W_ip) {
    int h = blockIdx.x;
    for (int k = threadIdx.x; k < NIN; k += blockDim.x) {
        float v = W_ip[h * NIN + k];                  // coalesced read
        g_Wip4[(k >> 2) * (NH * 4) + h * 4 + (k & 3)] = v;
    }
}

// ---------------- K2: c = x @ W_ip^T + b_ip + bq  (4096x784x256 fp32 GEMM) -------------
__global__ void __launch_bounds__(256, 1) k_xproj(const float* __restrict__ x,
                                                  const float* __restrict__ b_ip) {
    const int h = threadIdx.x;
    const int row0 = blockIdx.x * ROWS_PER_CTA;
    __shared__ float xS[196 * 36];                    // [c][r] transposed chunk, stride 36 (16B aligned)
    float acc[ROWS_PER_CTA];
#pragma unroll
    for (int r = 0; r < ROWS_PER_CTA; ++r) acc[r] = 0.0f;

    const float4* W4 = (const float4*)g_Wip4;
    for (int ch = 0; ch < 4; ++ch) {                  // 784 = 4 * 196
        __syncthreads();
        for (int idx = h; idx < ROWS_PER_CTA * 196; idx += 256) {
            int r = idx / 196, c = idx % 196;
            xS[c * 36 + r] = x[(row0 + r) * NIN + ch * 196 + c];
        }
        __syncthreads();
        float4 wnext = W4[(ch * 49) * NH + h];
        for (int k4 = 0; k4 < 49; ++k4) {
            float4 w = wnext;
            int kn = (k4 + 1 < 49) ? k4 + 1 : 48;
            wnext = W4[(ch * 49 + kn) * NH + h];
#pragma unroll
            for (int kk = 0; kk < 4; ++kk) {
                const float wv = ((const float*)&w)[kk];
                const float* tb = &xS[(k4 * 4 + kk) * 36];
#pragma unroll
                for (int r4 = 0; r4 < 8; ++r4) {
                    float4 tv = *(const float4*)(tb + r4 * 4);
                    acc[r4 * 4 + 0] = fmaf(tv.x, wv, acc[r4 * 4 + 0]);
                    acc[r4 * 4 + 1] = fmaf(tv.y, wv, acc[r4 * 4 + 1]);
                    acc[r4 * 4 + 2] = fmaf(tv.z, wv, acc[r4 * 4 + 2]);
                    acc[r4 * 4 + 3] = fmaf(tv.w, wv, acc[r4 * 4 + 3]);
                }
            }
        }
    }
    const float addend = b_ip[h] + g_bq[h];
#pragma unroll
    for (int r = 0; r < ROWS_PER_CTA; ++r)
        g_c[(row0 + r) * NH + h] = acc[r] + addend;
}

// ---------------- K3: persistent fixed-point iteration + output GEMM ----------------
__global__ void __launch_bounds__(256, 1) k_iter(const float* __restrict__ Wop,
                                                 const float* __restrict__ bop,
                                                 float* __restrict__ out) {
    const int h = threadIdx.x;
    const int row0 = blockIdx.x * ROWS_PER_CTA;
    __shared__ float tS[NH * 36];                     // [k][r], stride 36 floats (16B aligned rows)
    __shared__ unsigned sWarp[8];
    __shared__ unsigned sSticky;
    __shared__ unsigned sFlag;
    if (h == 0) sSticky = 0u;

    float cReg[ROWS_PER_CTA], sReg[ROWS_PER_CTA];
#pragma unroll
    for (int r = 0; r < ROWS_PER_CTA; ++r) {
        cReg[r] = g_c[(row0 + r) * NH + h];
        sReg[r] = cReg[r];                            // s0 = bq + x_proj
    }
    const float alpha = g_ab[0];
    const float beta  = g_ab[1];
    const float4* W4 = (const float4*)g_Wq4;
    __syncthreads();

    for (int it = 0; it < MAXIT; ++it) {
        // ---- tanh(s) -> shared (broadcast layout) ----
#pragma unroll
        for (int r = 0; r < ROWS_PER_CTA; ++r) {
            float t;
            asm("tanh.approx.f32 %0, %1;" : "=f"(t) : "f"(sReg[r]));
            tS[h * 36 + r] = t;
        }
        __syncthreads();

        // ---- acc[r] = sum_k tanh(s[r][k]) * Wq[h][k] ----
        float acc[ROWS_PER_CTA];
#pragma unroll
        for (int r = 0; r < ROWS_PER_CTA; ++r) acc[r] = 0.0f;
        float4 wnext = W4[h];
        for (int k4 = 0; k4 < 64; ++k4) {
            float4 w = wnext;
            int kn = (k4 + 1 < 64) ? k4 + 1 : 63;
            wnext = W4[kn * NH + h];
#pragma unroll
            for (int kk = 0; kk < 4; ++kk) {
                const float wv = ((const float*)&w)[kk];
                const float* tb = &tS[(k4 * 4 + kk) * 36];
#pragma unroll
                for (int r4 = 0; r4 < 8; ++r4) {
                    float4 tv = *(const float4*)(tb + r4 * 4);
                    acc[r4 * 4 + 0] = fmaf(tv.x, wv, acc[r4 * 4 + 0]);
                    acc[r4 * 4 + 1] = fmaf(tv.y, wv, acc[r4 * 4 + 1]);
                    acc[r4 * 4 + 2] = fmaf(tv.z, wv, acc[r4 * 4 + 2]);
                    acc[r4 * 4 + 3] = fmaf(tv.w, wv, acc[r4 * 4 + 3]);
                }
            }
        }
        __syncthreads();                              // tS reads done before next-iter writes

        // ---- update + per-row convergence bits ----
        unsigned convMask = 0u;
#pragma unroll
        for (int r = 0; r < ROWS_PER_CTA; ++r) {
            float sn = fmaf(alpha, sReg[r], fmaf(beta, acc[r], cReg[r]));
            float d = fabsf(sn - sReg[r]);
            sReg[r] = sn;
            convMask |= (d < TOLV ? 1u : 0u) << r;
        }
        unsigned wAnd = __reduce_and_sync(0xFFFFFFFFu, convMask);
        if ((h & 31) == 0) sWarp[h >> 5] = wAnd;
        __syncthreads();

        // ---- grid barrier slot `it` with packed all-converged vote ----
        if (h == 0) {
            unsigned m = 0xFFFFFFFFu;
#pragma unroll
            for (int wg = 0; wg < 8; ++wg) m &= sWarp[wg];
            unsigned sticky = sSticky | m;             // sticky per-row convergence (conv | diff<tol)
            sSticky = sticky;
            bool allc = (sticky == 0xFFFFFFFFu);
            unsigned add = 1u + (allc ? 0u : 0x10000u);
            atomicAdd(&g_bar[it], add);
            unsigned v;
            do {
                asm volatile("ld.acquire.gpu.u32 %0, [%1];" : "=r"(v) : "l"(&g_bar[it]) : "memory");
            } while ((v & 0xFFFFu) < (unsigned)NCTA);
            sFlag = ((v >> 16) == 0u) ? 1u : 0u;      // every CTA had all rows converged
        }
        __syncthreads();
        if (sFlag) break;
    }

    // ---- epilogue: out = s @ W_op^T + b_op ----
#pragma unroll
    for (int r = 0; r < ROWS_PER_CTA; ++r) tS[h * 36 + r] = sReg[r];
    __syncthreads();
    for (int idx = h; idx < ROWS_PER_CTA * NOUT; idx += 256) {
        int r = idx / NOUT, o = idx % NOUT;
        float a = bop[o];
        for (int k = 0; k < NH; ++k)
            a = fmaf(tS[k * 36 + r], Wop[o * NH + k], a);
        out[(row0 + r) * NOUT + o] = a;
    }
}

// ---------------- launch ----------------
extern "C" void kernel_launch(void* const* d_in, const int* in_sizes, int n_in,
                              void* d_out, int out_size) {
    // size-based mapping (robust to reordering; ties broken by original order)
    const float *x = nullptr, *W_ip = nullptr, *b_ip = nullptr, *W_op = nullptr,
                *b_op = nullptr, *W_raw = nullptr, *b_raw = nullptr,
                *a_raw = nullptr, *be_raw = nullptr;
    for (int i = 0; i < n_in; ++i) {
        const float* p = (const float*)d_in[i];
        switch (in_sizes[i]) {
            case NB * NIN:  x = p; break;
            case NH * NIN:  W_ip = p; break;
            case NH * NH:   W_raw = p; break;
            case NOUT * NH: W_op = p; break;
            case NOUT:      b_op = p; break;
            case NH:        if (!b_ip) b_ip = p; else b_raw = p; break;
            case 1:         if (!a_raw) a_raw = p; else be_raw = p; break;
            default: break;
        }
    }

    k_setup<<<NH + 1, NH>>>(W_raw, b_raw, a_raw, be_raw);
    k_packWip<<<NH, 256>>>(W_ip);
    k_xproj<<<NCTA, 256>>>(x, b_ip);
    k_iter<<<NCTA, 256>>>(W_op, b_op, (float*)d_out);
}

// round 5
// speedup vs baseline: 2.8899x; 2.8899x over previous
#include <cuda_runtime.h>
#include <cuda_fp16.h>
#include <cstdint>
#include <math.h>

// Problem: B=4096, IN=784, H=256, OUT=10, TOL=1e-3, MAX_ITERS=200
#define NB 4096
#define NIN 784
#define NH 256
#define NOUT 10
#define TOLV 1e-3f
#define MAXIT 200

#define ROWS 32
#define NCTA (NB / ROWS)                 // 128 CTAs <= 148 SMs -> co-resident
#define TPB 256                          // 8 warps

// SMEM layout for k_iter (dynamic):
//   [0, 135168)        Wq fp16, 256 rows x 264 halves (row stride 528B, +16B pad)
//   [135168, 152064)   A tile fp16, 32 rows x 264 halves
//   [152064, 152192)   sRowMax[32] (uint)
//   [152192, 152196)   sFlag
#define WQ_STRIDE 528
#define AS_OFF 135168
#define VOTE_OFF 152064
#define FLAG_OFF 152192
#define IT_SMEM 152320

// ---------------- device scratch ----------------
__device__ __half g_Wq16[NH * NH];       // fp16 integers round(tanh(W)*255), row-major [n][k]
__device__ float g_bq[NH];
__device__ float g_ab[2];                // alpha, beta
__device__ float g_Wip4[NIN * NH];       // W_ip^T packed [(k>>2)][h][k&3]
__device__ float g_c[NB * NH];           // c = bq + b_ip + x@W_ip^T, row-major
__device__ unsigned g_bar[256];          // grid-barrier slots

// ---------------- helpers ----------------
__device__ __forceinline__ uint32_t smem_u32(const void* p) {
    uint32_t r;
    asm("{ .reg .u64 t; cvta.to.shared.u64 t, %1; cvt.u32.u64 %0, t; }" : "=r"(r) : "l"(p));
    return r;
}
__device__ __forceinline__ float tanh_f32(float x) {
    float t;
    asm("tanh.approx.f32 %0, %1;" : "=f"(t) : "f"(x));
    return t;
}
__device__ __forceinline__ void ldsm_x4(uint32_t a, uint32_t& r0, uint32_t& r1,
                                        uint32_t& r2, uint32_t& r3) {
    asm volatile("ldmatrix.sync.aligned.m8n8.x4.shared.b16 {%0,%1,%2,%3}, [%4];"
                 : "=r"(r0), "=r"(r1), "=r"(r2), "=r"(r3) : "r"(a));
}
__device__ __forceinline__ void hmma(float* c, const uint32_t* a, const uint32_t* b) {
    asm volatile("mma.sync.aligned.m16n8k16.row.col.f32.f16.f16.f32 "
                 "{%0,%1,%2,%3}, {%4,%5,%6,%7}, {%8,%9}, {%0,%1,%2,%3};"
                 : "+f"(c[0]), "+f"(c[1]), "+f"(c[2]), "+f"(c[3])
                 : "r"(a[0]), "r"(a[1]), "r"(a[2]), "r"(a[3]), "r"(b[0]), "r"(b[1]));
}

// ---------------- K0: quantize, alpha/beta, zero barriers ----------------
__global__ void k_setup(const float* __restrict__ W_raw, const float* __restrict__ b_raw,
                        const float* __restrict__ a_raw, const float* __restrict__ be_raw) {
    int t = threadIdx.x;
    if (blockIdx.x < NH) {
        int n = blockIdx.x;
        float w = W_raw[n * NH + t];
        float q = rintf(tanhf(w) * 255.0f);
        q = fminf(fmaxf(q, -256.0f), 255.0f);
        g_Wq16[n * NH + t] = __float2half_rn(q);   // exact integer in fp16
    } else {
        float b = b_raw[t];
        float q = rintf(tanhf(b) * 255.0f);
        q = fminf(fmaxf(q, -256.0f), 255.0f);
        g_bq[t] = q / 255.0f;
        g_bar[t] = 0u;
        if (t == 0) {
            g_ab[0] = 1.0f / (1.0f + expf(-a_raw[0]));
            g_ab[1] = 1.0f / (1.0f + expf(-be_raw[0]));
        }
    }
}

// ---------------- K1: repack W_ip ----------------
__global__ void k_packWip(const float* __restrict__ W_ip) {
    int h = blockIdx.x;
    for (int k = threadIdx.x; k < NIN; k += blockDim.x) {
        float v = W_ip[h * NIN + k];
        g_Wip4[(k >> 2) * (NH * 4) + h * 4 + (k & 3)] = v;
    }
}

// ---------------- K2: c = x @ W_ip^T + b_ip + bq (fp32, proven R2 kernel) ----------------
__global__ void __launch_bounds__(256, 1) k_xproj(const float* __restrict__ x,
                                                  const float* __restrict__ b_ip) {
    const int h = threadIdx.x;
    const int row0 = blockIdx.x * ROWS;
    __shared__ float xS[196 * 36];
    float acc[ROWS];
#pragma unroll
    for (int r = 0; r < ROWS; ++r) acc[r] = 0.0f;

    const float4* W4 = (const float4*)g_Wip4;
    for (int ch = 0; ch < 4; ++ch) {
        __syncthreads();
        for (int idx = h; idx < ROWS * 196; idx += 256) {
            int r = idx / 196, c = idx % 196;
            xS[c * 36 + r] = x[(row0 + r) * NIN + ch * 196 + c];
        }
        __syncthreads();
        float4 wnext = W4[(ch * 49) * NH + h];
        for (int k4 = 0; k4 < 49; ++k4) {
            float4 w = wnext;
            int kn = (k4 + 1 < 49) ? k4 + 1 : 48;
            wnext = W4[(ch * 49 + kn) * NH + h];
#pragma unroll
            for (int kk = 0; kk < 4; ++kk) {
                const float wv = ((const float*)&w)[kk];
                const float* tb = &xS[(k4 * 4 + kk) * 36];
#pragma unroll
                for (int r4 = 0; r4 < 8; ++r4) {
                    float4 tv = *(const float4*)(tb + r4 * 4);
                    acc[r4 * 4 + 0] = fmaf(tv.x, wv, acc[r4 * 4 + 0]);
                    acc[r4 * 4 + 1] = fmaf(tv.y, wv, acc[r4 * 4 + 1]);
                    acc[r4 * 4 + 2] = fmaf(tv.z, wv, acc[r4 * 4 + 2]);
                    acc[r4 * 4 + 3] = fmaf(tv.w, wv, acc[r4 * 4 + 3]);
                }
            }
        }
    }
    const float addend = b_ip[h] + g_bq[h];
#pragma unroll
    for (int r = 0; r < ROWS; ++r)
        g_c[(row0 + r) * NH + h] = acc[r] + addend;
}

// ---------------- K3: persistent HMMA fixed-point iteration + output GEMM ----------------
// 128 CTAs x 256 thr. Warp w owns cols [32w,32w+32) (4 n8 tiles), all 32 rows (2 m16).
// s and c in C-fragment registers: s[mt][nt][e], row = 16mt + (l>>2) + 8(e>>1),
// col = 32w + 8nt + 2(l&3) + (e&1).
__global__ void __launch_bounds__(TPB, 1) k_iter(const float* __restrict__ Wop,
                                                 const float* __restrict__ bop,
                                                 float* __restrict__ out) {
    extern __shared__ char smem[];
    const uint32_t sbase = smem_u32(smem);
    const int tid = threadIdx.x;
    const int w = tid >> 5, l = tid & 31;
    const int r0 = l >> 2, c0 = (l & 3) * 2;
    const int colBase = w * 32;
    const int row0 = blockIdx.x * ROWS;

    unsigned* sRowMax = (unsigned*)(smem + VOTE_OFF);
    unsigned* sFlag   = (unsigned*)(smem + FLAG_OFF);
    if (tid < 32) sRowMax[tid] = 0u;

    // ---- stage Wq into padded SMEM (row n at byte n*528) ----
    {
        const int4* src = (const int4*)g_Wq16;
        int4* dst = (int4*)smem;
        for (int i = tid; i < NH * 32; i += TPB) {       // 32 int4 per row
            int n = i >> 5, kk = i & 31;
            dst[n * 33 + kk] = src[i];
        }
    }

    // ---- preload c and s0 in fragment layout ----
    float cR[2][4][4], s[2][4][4];
#pragma unroll
    for (int mt = 0; mt < 2; ++mt)
#pragma unroll
        for (int nt = 0; nt < 4; ++nt)
#pragma unroll
            for (int e = 0; e < 4; ++e) {
                int row = mt * 16 + r0 + 8 * (e >> 1);
                int col = colBase + nt * 8 + c0 + (e & 1);
                float v = g_c[(row0 + row) * NH + col];
                cR[mt][nt][e] = v;
                s[mt][nt][e] = v;
            }

    const float alpha = g_ab[0];
    const float betaS = g_ab[1] * (1.0f / 255.0f);
    __syncthreads();

    // lane-constant ldmatrix address pieces
    const uint32_t aAddr0 = sbase + AS_OFF + (uint32_t)((l & 15) * WQ_STRIDE + ((l & 16) >> 1) * 2);
    const uint32_t bAddrN = sbase + (uint32_t)(((l & 7) + ((l & 16) >> 1)) * WQ_STRIDE + (l & 8) * 2);
    unsigned sticky = 0u;

#pragma unroll 1
    for (int it = 0; it < MAXIT; ++it) {
        // ---- 1. tanh(s) -> fp16 A tile in SMEM ----
#pragma unroll
        for (int mt = 0; mt < 2; ++mt)
#pragma unroll
            for (int nt = 0; nt < 4; ++nt)
#pragma unroll
                for (int ep = 0; ep < 2; ++ep) {
                    float t0 = tanh_f32(s[mt][nt][ep * 2 + 0]);
                    float t1 = tanh_f32(s[mt][nt][ep * 2 + 1]);
                    uint32_t pk;
                    asm("cvt.rn.f16x2.f32 %0, %1, %2;" : "=r"(pk) : "f"(t1), "f"(t0));
                    int row = mt * 16 + r0 + 8 * ep;
                    int col = colBase + nt * 8 + c0;
                    *(uint32_t*)(smem + AS_OFF + row * WQ_STRIDE + col * 2) = pk;
                }
        __syncthreads();

        // ---- 2. acc = tanh(s) @ Wq^T via HMMA ----
        float acc[2][4][4];
#pragma unroll
        for (int mt = 0; mt < 2; ++mt)
#pragma unroll
            for (int nt = 0; nt < 4; ++nt)
#pragma unroll
                for (int e = 0; e < 4; ++e) acc[mt][nt][e] = 0.0f;

#pragma unroll 4
        for (int ks = 0; ks < 16; ++ks) {
            const uint32_t kb = (uint32_t)(ks * 32);      // 16 halves = 32 bytes
            uint32_t aF[2][4], bF[2][4];
#pragma unroll
            for (int mt = 0; mt < 2; ++mt)
                ldsm_x4(aAddr0 + (uint32_t)(mt * 16 * WQ_STRIDE) + kb,
                        aF[mt][0], aF[mt][1], aF[mt][2], aF[mt][3]);
#pragma unroll
            for (int np = 0; np < 2; ++np)
                ldsm_x4(bAddrN + (uint32_t)((colBase + np * 16) * WQ_STRIDE) + kb,
                        bF[np][0], bF[np][1], bF[np][2], bF[np][3]);
#pragma unroll
            for (int mt = 0; mt < 2; ++mt)
#pragma unroll
                for (int nt = 0; nt < 4; ++nt)
                    hmma(acc[mt][nt], aF[mt], &bF[nt >> 1][(nt & 1) * 2]);
        }

        // ---- 3. update s + per-row inf-norm ----
        float dmax[4] = {0.0f, 0.0f, 0.0f, 0.0f};
#pragma unroll
        for (int mt = 0; mt < 2; ++mt)
#pragma unroll
            for (int nt = 0; nt < 4; ++nt)
#pragma unroll
                for (int e = 0; e < 4; ++e) {
                    float sv = s[mt][nt][e];
                    float sn = fmaf(alpha, sv, fmaf(betaS, acc[mt][nt][e], cR[mt][nt][e]));
                    int j = mt * 2 + (e >> 1);
                    dmax[j] = fmaxf(dmax[j], fabsf(sn - sv));
                    s[mt][nt][e] = sn;
                }
#pragma unroll
        for (int off = 1; off <= 2; off <<= 1)
#pragma unroll
            for (int j = 0; j < 4; ++j)
                dmax[j] = fmaxf(dmax[j], __shfl_xor_sync(0xFFFFFFFFu, dmax[j], off));
        if ((l & 3) == 0) {
#pragma unroll
            for (int j = 0; j < 4; ++j)
                atomicMax((int*)&sRowMax[r0 + 8 * j], __float_as_int(dmax[j]));
        }
        __syncthreads();

        // ---- 4. grid-wide vote barrier ----
        if (tid < 32) {
            float v = __int_as_float((int)sRowMax[tid]);
            unsigned bal = __ballot_sync(0xFFFFFFFFu, v < TOLV);
            sRowMax[tid] = 0u;                           // reset for next iter
            if (tid == 0) {
                sticky |= bal;                            // sticky conv |= (diff < tol)
                unsigned add = 1u + ((sticky == 0xFFFFFFFFu) ? 0u : 0x10000u);
                atomicAdd(&g_bar[it], add);
                unsigned vv;
                do {
                    asm volatile("ld.acquire.gpu.u32 %0, [%1];" : "=r"(vv) : "l"(&g_bar[it]) : "memory");
                } while ((vv & 0xFFFFu) < (unsigned)NCTA);
                *sFlag = ((vv >> 16) == 0u) ? 1u : 0u;
            }
        }
        __syncthreads();
        if (*sFlag) break;
    }

    // ---- epilogue: out = s @ Wop^T + bop ----
    __syncthreads();
    float* wopS = (float*)smem;                           // 10x256 f32
    float* partS = (float*)(smem + 10240);                // [row][warp][10]
    for (int i = tid; i < NOUT * NH; i += TPB) wopS[i] = Wop[i];
    __syncthreads();
    float part[4][NOUT];
#pragma unroll
    for (int j = 0; j < 4; ++j) {
#pragma unroll
        for (int o = 0; o < NOUT; ++o) part[j][o] = 0.0f;
        int mt = j >> 1, eb = (j & 1) * 2;
#pragma unroll
        for (int nt = 0; nt < 4; ++nt)
#pragma unroll
            for (int b = 0; b < 2; ++b) {
                float sv = s[mt][nt][eb + b];
                int col = colBase + nt * 8 + c0 + b;
#pragma unroll
                for (int o = 0; o < NOUT; ++o)
                    part[j][o] = fmaf(sv, wopS[o * NH + col], part[j][o]);
            }
    }
#pragma unroll
    for (int off = 1; off <= 2; off <<= 1)
#pragma unroll
        for (int j = 0; j < 4; ++j)
#pragma unroll
            for (int o = 0; o < NOUT; ++o)
                part[j][o] += __shfl_xor_sync(0xFFFFFFFFu, part[j][o], off);
    if ((l & 3) == 0) {
#pragma unroll
        for (int j = 0; j < 4; ++j)
#pragma unroll
            for (int o = 0; o < NOUT; ++o)
                partS[((r0 + 8 * j) * 8 + w) * NOUT + o] = part[j][o];
    }
    __syncthreads();
    for (int i = tid; i < ROWS * NOUT; i += TPB) {
        int row = i / NOUT, o = i % NOUT;
        float v = bop[o];
#pragma unroll
        for (int ww = 0; ww < 8; ++ww)
            v += partS[(row * 8 + ww) * NOUT + o];
        out[(row0 + row) * NOUT + o] = v;
    }
}

// ---------------- launch ----------------
extern "C" void kernel_launch(void* const* d_in, const int* in_sizes, int n_in,
                              void* d_out, int out_size) {
    const float *x = nullptr, *W_ip = nullptr, *b_ip = nullptr, *W_op = nullptr,
                *b_op = nullptr, *W_raw = nullptr, *b_raw = nullptr,
                *a_raw = nullptr, *be_raw = nullptr;
    for (int i = 0; i < n_in; ++i) {
        const float* p = (const float*)d_in[i];
        switch (in_sizes[i]) {
            case NB * NIN:  x = p; break;
            case NH * NIN:  W_ip = p; break;
            case NH * NH:   W_raw = p; break;
            case NOUT * NH: W_op = p; break;
            case NOUT:      b_op = p; break;
            case NH:        if (!b_ip) b_ip = p; else b_raw = p; break;
            case 1:         if (!a_raw) a_raw = p; else be_raw = p; break;
            default: break;
        }
    }

    cudaFuncSetAttribute(k_iter, cudaFuncAttributeMaxDynamicSharedMemorySize, IT_SMEM);

    k_setup<<<NH + 1, NH>>>(W_raw, b_raw, a_raw, be_raw);
    k_packWip<<<NH, 256>>>(W_ip);
    k_xproj<<<NCTA, 256>>>(x, b_ip);
    k_iter<<<NCTA, TPB, IT_SMEM>>>(W_op, b_op, (float*)d_out);
}

// round 6
// speedup vs baseline: 4.4004x; 1.5227x over previous
#include <cuda_runtime.h>
#include <cuda_fp16.h>
#include <cstdint>
#include <math.h>

// Problem: B=4096, IN=784, H=256, OUT=10, TOL=1e-3, MAX_ITERS=200
#define NB 4096
#define NIN 784
#define NH 256
#define NOUT 10
#define TOLV 1e-3f
#define MAXIT 200

#define ROWS 32
#define NCTA (NB / ROWS)                 // 128 CTAs <= 148 SMs -> co-resident
#define TPB 256                          // 8 warps

// ---- k_iter SMEM layout (unchanged from R5) ----
#define WQ_STRIDE 528
#define AS_OFF 135168
#define VOTE_OFF 152064
#define FLAG_OFF 152192
#define IT_SMEM 152320

// ---- k_xproj SMEM layout ----
// B chunk: 256 n-rows x 112 k-halves, row stride 240B (15x16B, odd -> conflict-free)
#define XP_BSTR 240
#define XP_BH_OFF 0
#define XP_BL_OFF 61440
#define XP_AH_OFF 122880
#define XP_AL_OFF 130560
#define XP_SMEM 138240
#define KCH 112                          // K chunk (7 k16-steps), 784 = 7*112
#define NCH 7

// ---------------- device scratch ----------------
__device__ __half g_Wq16[NH * NH];       // fp16 integers round(tanh(W)*255), row-major [n][k]
__device__ float g_ab[2];                // alpha, beta
__device__ float g_add[NH];              // b_ip + bq
__device__ __half g_Wh[NIN * NH];        // W_ip hi, chunk-major: [kc][n][112]
__device__ __half g_Wl[NIN * NH];        // W_ip lo, same layout
__device__ float g_c[NB * NH];           // c = bq + b_ip + x@W_ip^T, row-major
__device__ unsigned g_bar[256];          // grid-barrier slots

// ---------------- helpers ----------------
__device__ __forceinline__ uint32_t smem_u32(const void* p) {
    uint32_t r;
    asm("{ .reg .u64 t; cvta.to.shared.u64 t, %1; cvt.u32.u64 %0, t; }" : "=r"(r) : "l"(p));
    return r;
}
__device__ __forceinline__ float tanh_f32(float x) {
    float t;
    asm("tanh.approx.f32 %0, %1;" : "=f"(t) : "f"(x));
    return t;
}
__device__ __forceinline__ void ldsm_x4(uint32_t a, uint32_t& r0, uint32_t& r1,
                                        uint32_t& r2, uint32_t& r3) {
    asm volatile("ldmatrix.sync.aligned.m8n8.x4.shared.b16 {%0,%1,%2,%3}, [%4];"
                 : "=r"(r0), "=r"(r1), "=r"(r2), "=r"(r3) : "r"(a));
}
__device__ __forceinline__ void hmma(float* c, const uint32_t* a, const uint32_t* b) {
    asm volatile("mma.sync.aligned.m16n8k16.row.col.f32.f16.f16.f32 "
                 "{%0,%1,%2,%3}, {%4,%5,%6,%7}, {%8,%9}, {%0,%1,%2,%3};"
                 : "+f"(c[0]), "+f"(c[1]), "+f"(c[2]), "+f"(c[3])
                 : "r"(a[0]), "r"(a[1]), "r"(a[2]), "r"(a[3]), "r"(b[0]), "r"(b[1]));
}

// ---------------- K0: quantize Wq/bq, alpha/beta, g_add, zero barriers ----------------
__global__ void k_setup(const float* __restrict__ W_raw, const float* __restrict__ b_raw,
                        const float* __restrict__ a_raw, const float* __restrict__ be_raw,
                        const float* __restrict__ b_ip) {
    int t = threadIdx.x;
    if (blockIdx.x < NH) {
        int n = blockIdx.x;
        float w = W_raw[n * NH + t];
        float q = rintf(tanhf(w) * 255.0f);
        q = fminf(fmaxf(q, -256.0f), 255.0f);
        g_Wq16[n * NH + t] = __float2half_rn(q);   // exact integer in fp16
    } else {
        float b = b_raw[t];
        float q = rintf(tanhf(b) * 255.0f);
        q = fminf(fmaxf(q, -256.0f), 255.0f);
        g_add[t] = b_ip[t] + q / 255.0f;           // b_ip + bq folded
        g_bar[t] = 0u;
        if (t == 0) {
            g_ab[0] = 1.0f / (1.0f + expf(-a_raw[0]));
            g_ab[1] = 1.0f / (1.0f + expf(-be_raw[0]));
        }
    }
}

// ---------------- K1: split W_ip into hi/lo fp16, chunk-major layout ----------------
__global__ void k_packWip(const float* __restrict__ W_ip) {
    int n = blockIdx.x;
    for (int k = threadIdx.x; k < NIN; k += blockDim.x) {
        float v = W_ip[n * NIN + k];
        __half h = __float2half_rn(v);
        __half lo = __float2half_rn(v - __half2float(h));
        int kc = k / KCH, kk = k % KCH;
        int dst = kc * (NH * KCH) + n * KCH + kk;
        g_Wh[dst] = h;
        g_Wl[dst] = lo;
    }
}

// ---------------- K2: c = x @ W_ip^T + b_ip + bq via split-fp16 HMMA ----------------
// 128 CTAs x 256 thr, 32 rows x 256 cols each. Warp w: cols [32w,32w+32), rows 0-31.
// C = xh@Wh + xh@Wl + xl@Wh (xl@Wl dropped, ~2^-22 relative).
__global__ void __launch_bounds__(TPB, 1) k_xproj(const float* __restrict__ x) {
    extern __shared__ char smem[];
    const uint32_t sbase = smem_u32(smem);
    const int tid = threadIdx.x;
    const int w = tid >> 5, l = tid & 31;
    const int r0 = l >> 2, c0 = (l & 3) * 2;
    const int colBase = w * 32;
    const int row0 = blockIdx.x * ROWS;

    float acc[2][4][4];
#pragma unroll
    for (int mt = 0; mt < 2; ++mt)
#pragma unroll
        for (int nt = 0; nt < 4; ++nt)
#pragma unroll
            for (int e = 0; e < 4; ++e) acc[mt][nt][e] = 0.0f;

    const uint32_t aPiece = (uint32_t)((l & 15) * XP_BSTR + (l & 16));
    const uint32_t bPiece = (uint32_t)(((l & 7) + ((l & 16) >> 1)) * XP_BSTR + (l & 8) * 2);
    const uint32_t aAddrH = sbase + XP_AH_OFF + aPiece;
    const uint32_t aAddrL = sbase + XP_AL_OFF + aPiece;
    const uint32_t bAddrH = sbase + XP_BH_OFF + bPiece;
    const uint32_t bAddrL = sbase + XP_BL_OFF + bPiece;

#pragma unroll 1
    for (int kc = 0; kc < NCH; ++kc) {
        __syncthreads();                              // prior compute done before overwrite
        // ---- stage B chunk (hi+lo), fully coalesced src ----
        {
            const uint4* srcH = (const uint4*)g_Wh + kc * (NH * KCH / 8);
            const uint4* srcL = (const uint4*)g_Wl + kc * (NH * KCH / 8);
            for (int idx = tid; idx < NH * (KCH / 8); idx += TPB) {   // 256*14
                int n = idx / 14, kk = idx - n * 14;
                uint32_t d = (uint32_t)(n * XP_BSTR + kk * 16);
                *(uint4*)(smem + XP_BH_OFF + d) = srcH[idx];
                *(uint4*)(smem + XP_BL_OFF + d) = srcL[idx];
            }
        }
        // ---- stage A chunk: split x on the fly ----
        for (int idx = tid; idx < ROWS * KCH; idx += TPB) {           // 3584
            int r = idx / KCH, k = idx - r * KCH;
            float v = x[(row0 + r) * NIN + kc * KCH + k];
            __half h = __float2half_rn(v);
            __half lo = __float2half_rn(v - __half2float(h));
            uint32_t d = (uint32_t)(r * XP_BSTR + k * 2);
            *(__half*)(smem + XP_AH_OFF + d) = h;
            *(__half*)(smem + XP_AL_OFF + d) = lo;
        }
        __syncthreads();

        // ---- 7 k16-steps ----
#pragma unroll
        for (int ks = 0; ks < 7; ++ks) {
            const uint32_t kb = (uint32_t)(ks * 32);
            uint32_t aH[2][4], aL[2][4], bH[2][4], bL[2][4];
#pragma unroll
            for (int mt = 0; mt < 2; ++mt) {
                ldsm_x4(aAddrH + (uint32_t)(mt * 16 * XP_BSTR) + kb,
                        aH[mt][0], aH[mt][1], aH[mt][2], aH[mt][3]);
                ldsm_x4(aAddrL + (uint32_t)(mt * 16 * XP_BSTR) + kb,
                        aL[mt][0], aL[mt][1], aL[mt][2], aL[mt][3]);
            }
#pragma unroll
            for (int np = 0; np < 2; ++np) {
                ldsm_x4(bAddrH + (uint32_t)((colBase + np * 16) * XP_BSTR) + kb,
                        bH[np][0], bH[np][1], bH[np][2], bH[np][3]);
                ldsm_x4(bAddrL + (uint32_t)((colBase + np * 16) * XP_BSTR) + kb,
                        bL[np][0], bL[np][1], bL[np][2], bL[np][3]);
            }
#pragma unroll
            for (int mt = 0; mt < 2; ++mt)
#pragma unroll
                for (int nt = 0; nt < 4; ++nt) {
                    uint32_t* bh = &bH[nt >> 1][(nt & 1) * 2];
                    uint32_t* bl = &bL[nt >> 1][(nt & 1) * 2];
                    hmma(acc[mt][nt], aH[mt], bh);
                    hmma(acc[mt][nt], aH[mt], bl);
                    hmma(acc[mt][nt], aL[mt], bh);
                }
        }
    }

    // ---- epilogue: += (b_ip + bq), store row-major ----
    float addv[4][2];
#pragma unroll
    for (int nt = 0; nt < 4; ++nt) {
        int col = colBase + nt * 8 + c0;
        addv[nt][0] = g_add[col];
        addv[nt][1] = g_add[col + 1];
    }
#pragma unroll
    for (int mt = 0; mt < 2; ++mt)
#pragma unroll
        for (int nt = 0; nt < 4; ++nt)
#pragma unroll
            for (int ep = 0; ep < 2; ++ep) {
                int row = row0 + mt * 16 + r0 + 8 * ep;
                int col = colBase + nt * 8 + c0;
                float2 v = make_float2(acc[mt][nt][ep * 2 + 0] + addv[nt][0],
                                       acc[mt][nt][ep * 2 + 1] + addv[nt][1]);
                *(float2*)&g_c[row * NH + col] = v;
            }
}

// ---------------- K3: persistent HMMA fixed-point iteration + output GEMM ----------------
// (unchanged from R5 — proven at 49.5us / rel_err 3.5e-6)
__global__ void __launch_bounds__(TPB, 1) k_iter(const float* __restrict__ Wop,
                                                 const float* __restrict__ bop,
                                                 float* __restrict__ out) {
    extern __shared__ char smem[];
    const uint32_t sbase = smem_u32(smem);
    const int tid = threadIdx.x;
    const int w = tid >> 5, l = tid & 31;
    const int r0 = l >> 2, c0 = (l & 3) * 2;
    const int colBase = w * 32;
    const int row0 = blockIdx.x * ROWS;

    unsigned* sRowMax = (unsigned*)(smem + VOTE_OFF);
    unsigned* sFlag   = (unsigned*)(smem + FLAG_OFF);
    if (tid < 32) sRowMax[tid] = 0u;

    // ---- stage Wq into padded SMEM (row n at byte n*528) ----
    {
        const int4* src = (const int4*)g_Wq16;
        int4* dst = (int4*)smem;
        for (int i = tid; i < NH * 32; i += TPB) {
            int n = i >> 5, kk = i & 31;
            dst[n * 33 + kk] = src[i];
        }
    }

    // ---- preload c and s0 in fragment layout ----
    float cR[2][4][4], s[2][4][4];
#pragma unroll
    for (int mt = 0; mt < 2; ++mt)
#pragma unroll
        for (int nt = 0; nt < 4; ++nt)
#pragma unroll
            for (int e = 0; e < 4; ++e) {
                int row = mt * 16 + r0 + 8 * (e >> 1);
                int col = colBase + nt * 8 + c0 + (e & 1);
                float v = g_c[(row0 + row) * NH + col];
                cR[mt][nt][e] = v;
                s[mt][nt][e] = v;
            }

    const float alpha = g_ab[0];
    const float betaS = g_ab[1] * (1.0f / 255.0f);
    __syncthreads();

    const uint32_t aAddr0 = sbase + AS_OFF + (uint32_t)((l & 15) * WQ_STRIDE + ((l & 16) >> 1) * 2);
    const uint32_t bAddrN = sbase + (uint32_t)(((l & 7) + ((l & 16) >> 1)) * WQ_STRIDE + (l & 8) * 2);
    unsigned sticky = 0u;

#pragma unroll 1
    for (int it = 0; it < MAXIT; ++it) {
        // ---- 1. tanh(s) -> fp16 A tile in SMEM ----
#pragma unroll
        for (int mt = 0; mt < 2; ++mt)
#pragma unroll
            for (int nt = 0; nt < 4; ++nt)
#pragma unroll
                for (int ep = 0; ep < 2; ++ep) {
                    float t0 = tanh_f32(s[mt][nt][ep * 2 + 0]);
                    float t1 = tanh_f32(s[mt][nt][ep * 2 + 1]);
                    uint32_t pk;
                    asm("cvt.rn.f16x2.f32 %0, %1, %2;" : "=r"(pk) : "f"(t1), "f"(t0));
                    int row = mt * 16 + r0 + 8 * ep;
                    int col = colBase + nt * 8 + c0;
                    *(uint32_t*)(smem + AS_OFF + row * WQ_STRIDE + col * 2) = pk;
                }
        __syncthreads();

        // ---- 2. acc = tanh(s) @ Wq^T via HMMA ----
        float acc[2][4][4];
#pragma unroll
        for (int mt = 0; mt < 2; ++mt)
#pragma unroll
            for (int nt = 0; nt < 4; ++nt)
#pragma unroll
                for (int e = 0; e < 4; ++e) acc[mt][nt][e] = 0.0f;

#pragma unroll 4
        for (int ks = 0; ks < 16; ++ks) {
            const uint32_t kb = (uint32_t)(ks * 32);
            uint32_t aF[2][4], bF[2][4];
#pragma unroll
            for (int mt = 0; mt < 2; ++mt)
                ldsm_x4(aAddr0 + (uint32_t)(mt * 16 * WQ_STRIDE) + kb,
                        aF[mt][0], aF[mt][1], aF[mt][2], aF[mt][3]);
#pragma unroll
            for (int np = 0; np < 2; ++np)
                ldsm_x4(bAddrN + (uint32_t)((colBase + np * 16) * WQ_STRIDE) + kb,
                        bF[np][0], bF[np][1], bF[np][2], bF[np][3]);
#pragma unroll
            for (int mt = 0; mt < 2; ++mt)
#pragma unroll
                for (int nt = 0; nt < 4; ++nt)
                    hmma(acc[mt][nt], aF[mt], &bF[nt >> 1][(nt & 1) * 2]);
        }

        // ---- 3. update s + per-row inf-norm ----
        float dmax[4] = {0.0f, 0.0f, 0.0f, 0.0f};
#pragma unroll
        for (int mt = 0; mt < 2; ++mt)
#pragma unroll
            for (int nt = 0; nt < 4; ++nt)
#pragma unroll
                for (int e = 0; e < 4; ++e) {
                    float sv = s[mt][nt][e];
                    float sn = fmaf(alpha, sv, fmaf(betaS, acc[mt][nt][e], cR[mt][nt][e]));
                    int j = mt * 2 + (e >> 1);
                    dmax[j] = fmaxf(dmax[j], fabsf(sn - sv));
                    s[mt][nt][e] = sn;
                }
#pragma unroll
        for (int off = 1; off <= 2; off <<= 1)
#pragma unroll
            for (int j = 0; j < 4; ++j)
                dmax[j] = fmaxf(dmax[j], __shfl_xor_sync(0xFFFFFFFFu, dmax[j], off));
        if ((l & 3) == 0) {
#pragma unroll
            for (int j = 0; j < 4; ++j)
                atomicMax((int*)&sRowMax[r0 + 8 * j], __float_as_int(dmax[j]));
        }
        __syncthreads();

        // ---- 4. grid-wide vote barrier ----
        if (tid < 32) {
            float v = __int_as_float((int)sRowMax[tid]);
            unsigned bal = __ballot_sync(0xFFFFFFFFu, v < TOLV);
            sRowMax[tid] = 0u;
            if (tid == 0) {
                sticky |= bal;
                unsigned add = 1u + ((sticky == 0xFFFFFFFFu) ? 0u : 0x10000u);
                atomicAdd(&g_bar[it], add);
                unsigned vv;
                do {
                    asm volatile("ld.acquire.gpu.u32 %0, [%1];" : "=r"(vv) : "l"(&g_bar[it]) : "memory");
                } while ((vv & 0xFFFFu) < (unsigned)NCTA);
                *sFlag = ((vv >> 16) == 0u) ? 1u : 0u;
            }
        }
        __syncthreads();
        if (*sFlag) break;
    }

    // ---- epilogue: out = s @ Wop^T + bop ----
    __syncthreads();
    float* wopS = (float*)smem;
    float* partS = (float*)(smem + 10240);
    for (int i = tid; i < NOUT * NH; i += TPB) wopS[i] = Wop[i];
    __syncthreads();
    float part[4][NOUT];
#pragma unroll
    for (int j = 0; j < 4; ++j) {
#pragma unroll
        for (int o = 0; o < NOUT; ++o) part[j][o] = 0.0f;
        int mt = j >> 1, eb = (j & 1) * 2;
#pragma unroll
        for (int nt = 0; nt < 4; ++nt)
#pragma unroll
            for (int b = 0; b < 2; ++b) {
                float sv = s[mt][nt][eb + b];
                int col = colBase + nt * 8 + c0 + b;
#pragma unroll
                for (int o = 0; o < NOUT; ++o)
                    part[j][o] = fmaf(sv, wopS[o * NH + col], part[j][o]);
            }
    }
#pragma unroll
    for (int off = 1; off <= 2; off <<= 1)
#pragma unroll
        for (int j = 0; j < 4; ++j)
#pragma unroll
            for (int o = 0; o < NOUT; ++o)
                part[j][o] += __shfl_xor_sync(0xFFFFFFFFu, part[j][o], off);
    if ((l & 3) == 0) {
#pragma unroll
        for (int j = 0; j < 4; ++j)
#pragma unroll
            for (int o = 0; o < NOUT; ++o)
                partS[((r0 + 8 * j) * 8 + w) * NOUT + o] = part[j][o];
    }
    __syncthreads();
    for (int i = tid; i < ROWS * NOUT; i += TPB) {
        int row = i / NOUT, o = i % NOUT;
        float v = bop[o];
#pragma unroll
        for (int ww = 0; ww < 8; ++ww)
            v += partS[(row * 8 + ww) * NOUT + o];
        out[(row0 + row) * NOUT + o] = v;
    }
}

// ---------------- launch ----------------
extern "C" void kernel_launch(void* const* d_in, const int* in_sizes, int n_in,
                              void* d_out, int out_size) {
    const float *x = nullptr, *W_ip = nullptr, *b_ip = nullptr, *W_op = nullptr,
                *b_op = nullptr, *W_raw = nullptr, *b_raw = nullptr,
                *a_raw = nullptr, *be_raw = nullptr;
    for (int i = 0; i < n_in; ++i) {
        const float* p = (const float*)d_in[i];
        switch (in_sizes[i]) {
            case NB * NIN:  x = p; break;
            case NH * NIN:  W_ip = p; break;
            case NH * NH:   W_raw = p; break;
            case NOUT * NH: W_op = p; break;
            case NOUT:      b_op = p; break;
            case NH:        if (!b_ip) b_ip = p; else b_raw = p; break;
            case 1:         if (!a_raw) a_raw = p; else be_raw = p; break;
            default: break;
        }
    }

    cudaFuncSetAttribute(k_xproj, cudaFuncAttributeMaxDynamicSharedMemorySize, XP_SMEM);
    cudaFuncSetAttribute(k_iter, cudaFuncAttributeMaxDynamicSharedMemorySize, IT_SMEM);

    k_setup<<<NH + 1, NH>>>(W_raw, b_raw, a_raw, be_raw, b_ip);
    k_packWip<<<NH, 256>>>(W_ip);
    k_xproj<<<NCTA, TPB, XP_SMEM>>>(x);
    k_iter<<<NCTA, TPB, IT_SMEM>>>(W_op, b_op, (float*)d_out);
}

// round 7
// speedup vs baseline: 5.0004x; 1.1364x over previous
#include <cuda_runtime.h>
#include <cuda_fp16.h>
#include <cstdint>
#include <math.h>

// Problem: B=4096, IN=784, H=256, OUT=10, TOL=1e-3, MAX_ITERS=200
#define NB 4096
#define NIN 784
#define NH 256
#define NOUT 10
#define TOLV 1e-3f
#define MAXIT 200

#define ROWS 32
#define NCTA (NB / ROWS)                 // 128 CTAs <= 148 SMs -> co-resident
#define TPB 256                          // 8 warps

// ---- k_iter SMEM layout ----
#define WQ_STRIDE 528
#define AS_OFF 135168                    // A tile: 32 x 528B
#define SW_OFF 152064                    // sW[8][32] floats = 1KB
#define FLAG_OFF 153088                  // sFlag, sRem
#define IT_SMEM 153216

// ---- k_xproj SMEM layout (unchanged from R6) ----
#define XP_BSTR 240
#define XP_BH_OFF 0
#define XP_BL_OFF 61440
#define XP_AH_OFF 122880
#define XP_AL_OFF 130560
#define XP_SMEM 138240
#define KCH 112
#define NCH 7

// ---------------- device scratch ----------------
__device__ __half g_Wq16[NH * NH];       // fp16 integers round(tanh(W)*255), row-major [n][k]
__device__ float g_ab[2];                // alpha, beta
__device__ float g_add[NH];              // b_ip + bq
__device__ __half g_Wh[NIN * NH];        // W_ip hi, chunk-major: [kc][n][112]
__device__ __half g_Wl[NIN * NH];        // W_ip lo, same layout
__device__ float g_c[NB * NH];           // c = bq + b_ip + x@W_ip^T, row-major
__device__ unsigned g_bar[4];            // single grid-barrier slot (+pad)
__device__ unsigned g_T;                 // global max iteration count

// ---------------- helpers ----------------
__device__ __forceinline__ uint32_t smem_u32(const void* p) {
    uint32_t r;
    asm("{ .reg .u64 t; cvta.to.shared.u64 t, %1; cvt.u32.u64 %0, t; }" : "=r"(r) : "l"(p));
    return r;
}
__device__ __forceinline__ float tanh_f32(float x) {
    float t;
    asm("tanh.approx.f32 %0, %1;" : "=f"(t) : "f"(x));
    return t;
}
__device__ __forceinline__ void ldsm_x4(uint32_t a, uint32_t& r0, uint32_t& r1,
                                        uint32_t& r2, uint32_t& r3) {
    asm volatile("ldmatrix.sync.aligned.m8n8.x4.shared.b16 {%0,%1,%2,%3}, [%4];"
                 : "=r"(r0), "=r"(r1), "=r"(r2), "=r"(r3) : "r"(a));
}
__device__ __forceinline__ void hmma(float* c, const uint32_t* a, const uint32_t* b) {
    asm volatile("mma.sync.aligned.m16n8k16.row.col.f32.f16.f16.f32 "
                 "{%0,%1,%2,%3}, {%4,%5,%6,%7}, {%8,%9}, {%0,%1,%2,%3};"
                 : "+f"(c[0]), "+f"(c[1]), "+f"(c[2]), "+f"(c[3])
                 : "r"(a[0]), "r"(a[1]), "r"(a[2]), "r"(a[3]), "r"(b[0]), "r"(b[1]));
}

// ---------------- K0: fused setup (Wq quantize | biases/ab/bars | W_ip split) -----------
__global__ void k_setup(const float* __restrict__ W_raw, const float* __restrict__ b_raw,
                        const float* __restrict__ a_raw, const float* __restrict__ be_raw,
                        const float* __restrict__ b_ip, const float* __restrict__ W_ip) {
    int b = blockIdx.x, t = threadIdx.x;
    if (b < NH) {                                   // Wq row b
        float w = W_raw[b * NH + t];
        float q = rintf(tanhf(w) * 255.0f);
        q = fminf(fmaxf(q, -256.0f), 255.0f);
        g_Wq16[b * NH + t] = __float2half_rn(q);    // exact integer in fp16
    } else if (b == NH) {                           // biases, scalars, barrier reset
        float bb = b_raw[t];
        float q = rintf(tanhf(bb) * 255.0f);
        q = fminf(fmaxf(q, -256.0f), 255.0f);
        g_add[t] = b_ip[t] + q / 255.0f;
        if (t < 4) g_bar[t] = 0u;
        if (t == 0) {
            g_T = 0u;
            g_ab[0] = 1.0f / (1.0f + expf(-a_raw[0]));
            g_ab[1] = 1.0f / (1.0f + expf(-be_raw[0]));
        }
    } else {                                        // W_ip row (b - NH - 1): hi/lo split
        int n = b - NH - 1;
        for (int k = t; k < NIN; k += blockDim.x) {
            float v = W_ip[n * NIN + k];
            __half h = __float2half_rn(v);
            __half lo = __float2half_rn(v - __half2float(h));
            int kc = k / KCH, kk = k % KCH;
            int dst = kc * (NH * KCH) + n * KCH + kk;
            g_Wh[dst] = h;
            g_Wl[dst] = lo;
        }
    }
}

// ---------------- K1: c = x @ W_ip^T + b_ip + bq via split-fp16 HMMA (proven R6) --------
__global__ void __launch_bounds__(TPB, 1) k_xproj(const float* __restrict__ x) {
    extern __shared__ char smem[];
    const uint32_t sbase = smem_u32(smem);
    const int tid = threadIdx.x;
    const int w = tid >> 5, l = tid & 31;
    const int r0 = l >> 2, c0 = (l & 3) * 2;
    const int colBase = w * 32;
    const int row0 = blockIdx.x * ROWS;

    float acc[2][4][4];
#pragma unroll
    for (int mt = 0; mt < 2; ++mt)
#pragma unroll
        for (int nt = 0; nt < 4; ++nt)
#pragma unroll
            for (int e = 0; e < 4; ++e) acc[mt][nt][e] = 0.0f;

    const uint32_t aPiece = (uint32_t)((l & 15) * XP_BSTR + (l & 16));
    const uint32_t bPiece = (uint32_t)(((l & 7) + ((l & 16) >> 1)) * XP_BSTR + (l & 8) * 2);
    const uint32_t aAddrH = sbase + XP_AH_OFF + aPiece;
    const uint32_t aAddrL = sbase + XP_AL_OFF + aPiece;
    const uint32_t bAddrH = sbase + XP_BH_OFF + bPiece;
    const uint32_t bAddrL = sbase + XP_BL_OFF + bPiece;

#pragma unroll 1
    for (int kc = 0; kc < NCH; ++kc) {
        __syncthreads();
        {
            const uint4* srcH = (const uint4*)g_Wh + kc * (NH * KCH / 8);
            const uint4* srcL = (const uint4*)g_Wl + kc * (NH * KCH / 8);
            for (int idx = tid; idx < NH * (KCH / 8); idx += TPB) {
                int n = idx / 14, kk = idx - n * 14;
                uint32_t d = (uint32_t)(n * XP_BSTR + kk * 16);
                *(uint4*)(smem + XP_BH_OFF + d) = srcH[idx];
                *(uint4*)(smem + XP_BL_OFF + d) = srcL[idx];
            }
        }
        for (int idx = tid; idx < ROWS * KCH; idx += TPB) {
            int r = idx / KCH, k = idx - r * KCH;
            float v = x[(row0 + r) * NIN + kc * KCH + k];
            __half h = __float2half_rn(v);
            __half lo = __float2half_rn(v - __half2float(h));
            uint32_t d = (uint32_t)(r * XP_BSTR + k * 2);
            *(__half*)(smem + XP_AH_OFF + d) = h;
            *(__half*)(smem + XP_AL_OFF + d) = lo;
        }
        __syncthreads();

#pragma unroll
        for (int ks = 0; ks < 7; ++ks) {
            const uint32_t kb = (uint32_t)(ks * 32);
            uint32_t aH[2][4], aL[2][4], bH[2][4], bL[2][4];
#pragma unroll
            for (int mt = 0; mt < 2; ++mt) {
                ldsm_x4(aAddrH + (uint32_t)(mt * 16 * XP_BSTR) + kb,
                        aH[mt][0], aH[mt][1], aH[mt][2], aH[mt][3]);
                ldsm_x4(aAddrL + (uint32_t)(mt * 16 * XP_BSTR) + kb,
                        aL[mt][0], aL[mt][1], aL[mt][2], aL[mt][3]);
            }
#pragma unroll
            for (int np = 0; np < 2; ++np) {
                ldsm_x4(bAddrH + (uint32_t)((colBase + np * 16) * XP_BSTR) + kb,
                        bH[np][0], bH[np][1], bH[np][2], bH[np][3]);
                ldsm_x4(bAddrL + (uint32_t)((colBase + np * 16) * XP_BSTR) + kb,
                        bL[np][0], bL[np][1], bL[np][2], bL[np][3]);
            }
#pragma unroll
            for (int mt = 0; mt < 2; ++mt)
#pragma unroll
                for (int nt = 0; nt < 4; ++nt) {
                    uint32_t* bh = &bH[nt >> 1][(nt & 1) * 2];
                    uint32_t* bl = &bL[nt >> 1][(nt & 1) * 2];
                    hmma(acc[mt][nt], aH[mt], bh);
                    hmma(acc[mt][nt], aH[mt], bl);
                    hmma(acc[mt][nt], aL[mt], bh);
                }
        }
    }

    float addv[4][2];
#pragma unroll
    for (int nt = 0; nt < 4; ++nt) {
        int col = colBase + nt * 8 + c0;
        addv[nt][0] = g_add[col];
        addv[nt][1] = g_add[col + 1];
    }
#pragma unroll
    for (int mt = 0; mt < 2; ++mt)
#pragma unroll
        for (int nt = 0; nt < 4; ++nt)
#pragma unroll
            for (int ep = 0; ep < 2; ++ep) {
                int row = row0 + mt * 16 + r0 + 8 * ep;
                int col = colBase + nt * 8 + c0;
                float2 v = make_float2(acc[mt][nt][ep * 2 + 0] + addv[nt][0],
                                       acc[mt][nt][ep * 2 + 1] + addv[nt][1]);
                *(float2*)&g_c[row * NH + col] = v;
            }
}

// ---------------- K2: two-phase HMMA fixed-point iteration + output GEMM ----------------
// Phase 1: free-running per-CTA until local sticky convergence (t_local).
// Single grid barrier: T = max(t_local).  Phase 2: counted T - t_local iterations.
// Row trajectories are independent -> bit-identical to per-iteration global sync.
__global__ void __launch_bounds__(TPB, 1) k_iter(const float* __restrict__ Wop,
                                                 const float* __restrict__ bop,
                                                 float* __restrict__ out) {
    extern __shared__ char smem[];
    const uint32_t sbase = smem_u32(smem);
    const int tid = threadIdx.x;
    const int w = tid >> 5, l = tid & 31;
    const int r0 = l >> 2, c0 = (l & 3) * 2;
    const int colBase = w * 32;
    const int row0 = blockIdx.x * ROWS;

    float* sW = (float*)(smem + SW_OFF);             // [warp][row] slice maxima
    unsigned* sFlag = (unsigned*)(smem + FLAG_OFF);
    unsigned* sRem  = (unsigned*)(smem + FLAG_OFF + 4);

    // ---- stage Wq into padded SMEM (row n at byte n*528) ----
    {
        const int4* src = (const int4*)g_Wq16;
        int4* dst = (int4*)smem;
        for (int i = tid; i < NH * 32; i += TPB) {
            int n = i >> 5, kk = i & 31;
            dst[n * 33 + kk] = src[i];
        }
    }

    // ---- preload c and s0 in fragment layout ----
    float cR[2][4][4], s[2][4][4];
#pragma unroll
    for (int mt = 0; mt < 2; ++mt)
#pragma unroll
        for (int nt = 0; nt < 4; ++nt)
#pragma unroll
            for (int e = 0; e < 4; ++e) {
                int row = mt * 16 + r0 + 8 * (e >> 1);
                int col = colBase + nt * 8 + c0 + (e & 1);
                float v = g_c[(row0 + row) * NH + col];
                cR[mt][nt][e] = v;
                s[mt][nt][e] = v;
            }

    const float alpha = g_ab[0];
    const float betaS = g_ab[1] * (1.0f / 255.0f);
    __syncthreads();

    const uint32_t aAddr0 = sbase + AS_OFF + (uint32_t)((l & 15) * WQ_STRIDE + ((l & 16) >> 1) * 2);
    const uint32_t bAddrN = sbase + (uint32_t)(((l & 7) + ((l & 16) >> 1)) * WQ_STRIDE + (l & 8) * 2);
    unsigned sticky = 0u;
    int done_it = MAXIT;

    // ================= PHASE 1: iterate until LOCAL convergence =================
#pragma unroll 1
    for (int it = 0; it < MAXIT; ++it) {
        // ---- 1. tanh(s) -> fp16 A tile in SMEM ----
#pragma unroll
        for (int mt = 0; mt < 2; ++mt)
#pragma unroll
            for (int nt = 0; nt < 4; ++nt)
#pragma unroll
                for (int ep = 0; ep < 2; ++ep) {
                    float t0 = tanh_f32(s[mt][nt][ep * 2 + 0]);
                    float t1 = tanh_f32(s[mt][nt][ep * 2 + 1]);
                    uint32_t pk;
                    asm("cvt.rn.f16x2.f32 %0, %1, %2;" : "=r"(pk) : "f"(t1), "f"(t0));
                    int row = mt * 16 + r0 + 8 * ep;
                    int col = colBase + nt * 8 + c0;
                    *(uint32_t*)(smem + AS_OFF + row * WQ_STRIDE + col * 2) = pk;
                }
        __syncthreads();

        // ---- 2. acc = tanh(s) @ Wq^T via HMMA ----
        float acc[2][4][4];
#pragma unroll
        for (int mt = 0; mt < 2; ++mt)
#pragma unroll
            for (int nt = 0; nt < 4; ++nt)
#pragma unroll
                for (int e = 0; e < 4; ++e) acc[mt][nt][e] = 0.0f;
#pragma unroll 4
        for (int ks = 0; ks < 16; ++ks) {
            const uint32_t kb = (uint32_t)(ks * 32);
            uint32_t aF[2][4], bF[2][4];
#pragma unroll
            for (int mt = 0; mt < 2; ++mt)
                ldsm_x4(aAddr0 + (uint32_t)(mt * 16 * WQ_STRIDE) + kb,
                        aF[mt][0], aF[mt][1], aF[mt][2], aF[mt][3]);
#pragma unroll
            for (int np = 0; np < 2; ++np)
                ldsm_x4(bAddrN + (uint32_t)((colBase + np * 16) * WQ_STRIDE) + kb,
                        bF[np][0], bF[np][1], bF[np][2], bF[np][3]);
#pragma unroll
            for (int mt = 0; mt < 2; ++mt)
#pragma unroll
                for (int nt = 0; nt < 4; ++nt)
                    hmma(acc[mt][nt], aF[mt], &bF[nt >> 1][(nt & 1) * 2]);
        }

        // ---- 3. update s + per-row slice inf-norm ----
        float dmax[4] = {0.0f, 0.0f, 0.0f, 0.0f};
#pragma unroll
        for (int mt = 0; mt < 2; ++mt)
#pragma unroll
            for (int nt = 0; nt < 4; ++nt)
#pragma unroll
                for (int e = 0; e < 4; ++e) {
                    float sv = s[mt][nt][e];
                    float sn = fmaf(alpha, sv, fmaf(betaS, acc[mt][nt][e], cR[mt][nt][e]));
                    int j = mt * 2 + (e >> 1);
                    dmax[j] = fmaxf(dmax[j], fabsf(sn - sv));
                    s[mt][nt][e] = sn;
                }
#pragma unroll
        for (int off = 1; off <= 2; off <<= 1)
#pragma unroll
            for (int j = 0; j < 4; ++j)
                dmax[j] = fmaxf(dmax[j], __shfl_xor_sync(0xFFFFFFFFu, dmax[j], off));
        if ((l & 3) == 0) {
#pragma unroll
            for (int j = 0; j < 4; ++j)
                sW[w * 32 + r0 + 8 * j] = dmax[j];
        }
        __syncthreads();

        // ---- 4. LOCAL vote (warp 0) ----
        if (tid < 32) {
            float m = sW[tid];
#pragma unroll
            for (int ww = 1; ww < 8; ++ww)
                m = fmaxf(m, sW[ww * 32 + tid]);
            unsigned bal = __ballot_sync(0xFFFFFFFFu, m < TOLV);
            sticky |= bal;                            // sticky conv |= (full-row diff < tol)
            if (tid == 0) *sFlag = (sticky == 0xFFFFFFFFu) ? 1u : 0u;
        }
        __syncthreads();
        if (*sFlag) { done_it = it + 1; break; }
    }

    // ================= single grid barrier: T = max(t_local) =================
    if (tid == 0) {
        atomicMax(&g_T, (unsigned)done_it);
        __threadfence();
        atomicAdd(&g_bar[0], 1u);
        unsigned vv;
        do {
            asm volatile("ld.acquire.gpu.u32 %0, [%1];" : "=r"(vv) : "l"(&g_bar[0]) : "memory");
        } while (vv < (unsigned)NCTA);
        unsigned tg;
        asm volatile("ld.acquire.gpu.u32 %0, [%1];" : "=r"(tg) : "l"(&g_T) : "memory");
        *sRem = tg;
    }
    __syncthreads();
    const int rem = (int)*sRem - done_it;

    // ================= PHASE 2: counted tail, no convergence checks =================
#pragma unroll 1
    for (int i = 0; i < rem; ++i) {
#pragma unroll
        for (int mt = 0; mt < 2; ++mt)
#pragma unroll
            for (int nt = 0; nt < 4; ++nt)
#pragma unroll
                for (int ep = 0; ep < 2; ++ep) {
                    float t0 = tanh_f32(s[mt][nt][ep * 2 + 0]);
                    float t1 = tanh_f32(s[mt][nt][ep * 2 + 1]);
                    uint32_t pk;
                    asm("cvt.rn.f16x2.f32 %0, %1, %2;" : "=r"(pk) : "f"(t1), "f"(t0));
                    int row = mt * 16 + r0 + 8 * ep;
                    int col = colBase + nt * 8 + c0;
                    *(uint32_t*)(smem + AS_OFF + row * WQ_STRIDE + col * 2) = pk;
                }
        __syncthreads();

        float acc[2][4][4];
#pragma unroll
        for (int mt = 0; mt < 2; ++mt)
#pragma unroll
            for (int nt = 0; nt < 4; ++nt)
#pragma unroll
                for (int e = 0; e < 4; ++e) acc[mt][nt][e] = 0.0f;
#pragma unroll 4
        for (int ks = 0; ks < 16; ++ks) {
            const uint32_t kb = (uint32_t)(ks * 32);
            uint32_t aF[2][4], bF[2][4];
#pragma unroll
            for (int mt = 0; mt < 2; ++mt)
                ldsm_x4(aAddr0 + (uint32_t)(mt * 16 * WQ_STRIDE) + kb,
                        aF[mt][0], aF[mt][1], aF[mt][2], aF[mt][3]);
#pragma unroll
            for (int np = 0; np < 2; ++np)
                ldsm_x4(bAddrN + (uint32_t)((colBase + np * 16) * WQ_STRIDE) + kb,
                        bF[np][0], bF[np][1], bF[np][2], bF[np][3]);
#pragma unroll
            for (int mt = 0; mt < 2; ++mt)
#pragma unroll
                for (int nt = 0; nt < 4; ++nt)
                    hmma(acc[mt][nt], aF[mt], &bF[nt >> 1][(nt & 1) * 2]);
        }
#pragma unroll
        for (int mt = 0; mt < 2; ++mt)
#pragma unroll
            for (int nt = 0; nt < 4; ++nt)
#pragma unroll
                for (int e = 0; e < 4; ++e)
                    s[mt][nt][e] = fmaf(alpha, s[mt][nt][e],
                                        fmaf(betaS, acc[mt][nt][e], cR[mt][nt][e]));
        __syncthreads();
    }

    // ---- epilogue: out = s @ Wop^T + bop ----
    __syncthreads();
    float* wopS = (float*)smem;
    float* partS = (float*)(smem + 10240);
    for (int i = tid; i < NOUT * NH; i += TPB) wopS[i] = Wop[i];
    __syncthreads();
    float part[4][NOUT];
#pragma unroll
    for (int j = 0; j < 4; ++j) {
#pragma unroll
        for (int o = 0; o < NOUT; ++o) part[j][o] = 0.0f;
        int mt = j >> 1, eb = (j & 1) * 2;
#pragma unroll
        for (int nt = 0; nt < 4; ++nt)
#pragma unroll
            for (int b = 0; b < 2; ++b) {
                float sv = s[mt][nt][eb + b];
                int col = colBase + nt * 8 + c0 + b;
#pragma unroll
                for (int o = 0; o < NOUT; ++o)
                    part[j][o] = fmaf(sv, wopS[o * NH + col], part[j][o]);
            }
    }
#pragma unroll
    for (int off = 1; off <= 2; off <<= 1)
#pragma unroll
        for (int j = 0; j < 4; ++j)
#pragma unroll
            for (int o = 0; o < NOUT; ++o)
                part[j][o] += __shfl_xor_sync(0xFFFFFFFFu, part[j][o], off);
    if ((l & 3) == 0) {
#pragma unroll
        for (int j = 0; j < 4; ++j)
#pragma unroll
            for (int o = 0; o < NOUT; ++o)
                partS[((r0 + 8 * j) * 8 + w) * NOUT + o] = part[j][o];
    }
    __syncthreads();
    for (int i = tid; i < ROWS * NOUT; i += TPB) {
        int row = i / NOUT, o = i % NOUT;
        float v = bop[o];
#pragma unroll
        for (int ww = 0; ww < 8; ++ww)
            v += partS[(row * 8 + ww) * NOUT + o];
        out[(row0 + row) * NOUT + o] = v;
    }
}

// ---------------- launch ----------------
extern "C" void kernel_launch(void* const* d_in, const int* in_sizes, int n_in,
                              void* d_out, int out_size) {
    const float *x = nullptr, *W_ip = nullptr, *b_ip = nullptr, *W_op = nullptr,
                *b_op = nullptr, *W_raw = nullptr, *b_raw = nullptr,
                *a_raw = nullptr, *be_raw = nullptr;
    for (int i = 0; i < n_in; ++i) {
        const float* p = (const float*)d_in[i];
        switch (in_sizes[i]) {
            case NB * NIN:  x = p; break;
            case NH * NIN:  W_ip = p; break;
            case NH * NH:   W_raw = p; break;
            case NOUT * NH: W_op = p; break;
            case NOUT:      b_op = p; break;
            case NH:        if (!b_ip) b_ip = p; else b_raw = p; break;
            case 1:         if (!a_raw) a_raw = p; else be_raw = p; break;
            default: break;
        }
    }

    cudaFuncSetAttribute(k_xproj, cudaFuncAttributeMaxDynamicSharedMemorySize, XP_SMEM);
    cudaFuncSetAttribute(k_iter, cudaFuncAttributeMaxDynamicSharedMemorySize, IT_SMEM);

    k_setup<<<2 * NH + 1, 256>>>(W_raw, b_raw, a_raw, be_raw, b_ip, W_ip);
    k_xproj<<<NCTA, TPB, XP_SMEM>>>(x);
    k_iter<<<NCTA, TPB, IT_SMEM>>>(W_op, b_op, (float*)d_out);
}

// round 8
// speedup vs baseline: 5.3059x; 1.0611x over previous
#include <cuda_runtime.h>
#include <cuda_fp16.h>
#include <cstdint>
#include <math.h>

// Problem: B=4096, IN=784, H=256, OUT=10, TOL=1e-3, MAX_ITERS=200
#define NB 4096
#define NIN 784
#define NH 256
#define NOUT 10
#define TOLV 1e-3f
#define MAXIT 200

#define ROWS 32
#define NCTA (NB / ROWS)                 // 128 CTAs <= 148 SMs -> co-resident
#define TPB 256                          // 8 warps

// ---- fused kernel SMEM layout ----
// iteration view:
#define WQ_STRIDE 528
#define AS0_OFF 135168                   // A tile buf0: 32 x 528B
#define AS1_OFF 152064                   // A tile buf1
#define SW_OFF 168960                    // sW[8][32] floats
#define REM_OFF 169984                   // sRem
#define SMEM_SZ 170240
// xproj view (lives in [0, 138240), used before Wq staging):
#define XP_BSTR 240
#define XP_BH_OFF 0
#define XP_BL_OFF 61440
#define XP_AH_OFF 122880
#define XP_AL_OFF 130560
#define KCH 112
#define NCH 7

// ---------------- device scratch ----------------
__device__ __half g_Wq16[NH * NH];       // fp16 integers round(tanh(W)*255), row-major [n][k]
__device__ float g_ab[2];                // alpha, beta
__device__ float g_add[NH];              // b_ip + bq
__device__ __half g_Wh[NIN * NH];        // W_ip hi, chunk-major: [kc][n][112]
__device__ __half g_Wl[NIN * NH];        // W_ip lo, same layout
__device__ unsigned g_bar[4];            // single grid-barrier slot
__device__ unsigned g_T;                 // global max iteration count

// ---------------- helpers ----------------
__device__ __forceinline__ uint32_t smem_u32(const void* p) {
    uint32_t r;
    asm("{ .reg .u64 t; cvta.to.shared.u64 t, %1; cvt.u32.u64 %0, t; }" : "=r"(r) : "l"(p));
    return r;
}
__device__ __forceinline__ float tanh_f32(float x) {
    float t;
    asm("tanh.approx.f32 %0, %1;" : "=f"(t) : "f"(x));
    return t;
}
__device__ __forceinline__ void ldsm_x4(uint32_t a, uint32_t& r0, uint32_t& r1,
                                        uint32_t& r2, uint32_t& r3) {
    asm volatile("ldmatrix.sync.aligned.m8n8.x4.shared.b16 {%0,%1,%2,%3}, [%4];"
                 : "=r"(r0), "=r"(r1), "=r"(r2), "=r"(r3) : "r"(a));
}
__device__ __forceinline__ void hmma(float* c, const uint32_t* a, const uint32_t* b) {
    asm volatile("mma.sync.aligned.m16n8k16.row.col.f32.f16.f16.f32 "
                 "{%0,%1,%2,%3}, {%4,%5,%6,%7}, {%8,%9}, {%0,%1,%2,%3};"
                 : "+f"(c[0]), "+f"(c[1]), "+f"(c[2]), "+f"(c[3])
                 : "r"(a[0]), "r"(a[1]), "r"(a[2]), "r"(a[3]), "r"(b[0]), "r"(b[1]));
}

// ---------------- K0: fused setup (Wq quantize | biases/ab/bars | W_ip split) -----------
__global__ void k_setup(const float* __restrict__ W_raw, const float* __restrict__ b_raw,
                        const float* __restrict__ a_raw, const float* __restrict__ be_raw,
                        const float* __restrict__ b_ip, const float* __restrict__ W_ip) {
    int b = blockIdx.x, t = threadIdx.x;
    if (b < NH) {                                   // Wq row b (coalesced)
        float w = W_raw[b * NH + t];
        float q = rintf(tanhf(w) * 255.0f);
        q = fminf(fmaxf(q, -256.0f), 255.0f);
        g_Wq16[b * NH + t] = __float2half_rn(q);    // exact integer in fp16
    } else if (b == NH) {                           // biases, scalars, barrier reset
        float bb = b_raw[t];
        float q = rintf(tanhf(bb) * 255.0f);
        q = fminf(fmaxf(q, -256.0f), 255.0f);
        g_add[t] = b_ip[t] + q / 255.0f;
        if (t < 4) g_bar[t] = 0u;
        if (t == 0) {
            g_T = 0u;
            g_ab[0] = 1.0f / (1.0f + expf(-a_raw[0]));
            g_ab[1] = 1.0f / (1.0f + expf(-be_raw[0]));
        }
    } else {                                        // W_ip row: hi/lo split, half2 stores
        int n = b - NH - 1;
        for (int k2 = t; k2 < NIN / 2; k2 += blockDim.x) {
            int k = 2 * k2;
            float v0 = W_ip[n * NIN + k];
            float v1 = W_ip[n * NIN + k + 1];
            __half h0 = __float2half_rn(v0), h1 = __float2half_rn(v1);
            __half l0 = __float2half_rn(v0 - __half2float(h0));
            __half l1 = __float2half_rn(v1 - __half2float(h1));
            int kc = k / KCH, kk = k % KCH;         // pairs never straddle chunks (112 even)
            int dst = kc * (NH * KCH) + n * KCH + kk;
            *(__half2*)&g_Wh[dst] = __halves2half2(h0, h1);
            *(__half2*)&g_Wl[dst] = __halves2half2(l0, l1);
        }
    }
}

// ---------------- K1: fused xproj + two-phase iteration + output GEMM ----------------
__global__ void __launch_bounds__(TPB, 1) k_main(const float* __restrict__ x,
                                                 const float* __restrict__ Wop,
                                                 const float* __restrict__ bop,
                                                 float* __restrict__ out) {
    extern __shared__ char smem[];
    const uint32_t sbase = smem_u32(smem);
    const int tid = threadIdx.x;
    const int w = tid >> 5, l = tid & 31;
    const int r0 = l >> 2, c0 = (l & 3) * 2;
    const int colBase = w * 32;
    const int row0 = blockIdx.x * ROWS;

    float* sW = (float*)(smem + SW_OFF);
    unsigned* sRem = (unsigned*)(smem + REM_OFF);

    // ================= xproj: c = x @ W_ip^T + b_ip + bq (split-fp16 HMMA) =================
    float cR[2][4][4];
#pragma unroll
    for (int mt = 0; mt < 2; ++mt)
#pragma unroll
        for (int nt = 0; nt < 4; ++nt)
#pragma unroll
            for (int e = 0; e < 4; ++e) cR[mt][nt][e] = 0.0f;
    {
        const uint32_t aPiece = (uint32_t)((l & 15) * XP_BSTR + (l & 16));
        const uint32_t bPiece = (uint32_t)(((l & 7) + ((l & 16) >> 1)) * XP_BSTR + (l & 8) * 2);
        const uint32_t aAddrH = sbase + XP_AH_OFF + aPiece;
        const uint32_t aAddrL = sbase + XP_AL_OFF + aPiece;
        const uint32_t bAddrH = sbase + XP_BH_OFF + bPiece;
        const uint32_t bAddrL = sbase + XP_BL_OFF + bPiece;

#pragma unroll 1
        for (int kc = 0; kc < NCH; ++kc) {
            __syncthreads();
            {
                const uint4* srcH = (const uint4*)g_Wh + kc * (NH * KCH / 8);
                const uint4* srcL = (const uint4*)g_Wl + kc * (NH * KCH / 8);
                for (int idx = tid; idx < NH * (KCH / 8); idx += TPB) {
                    int n = idx / 14, kk = idx - n * 14;
                    uint32_t d = (uint32_t)(n * XP_BSTR + kk * 16);
                    *(uint4*)(smem + XP_BH_OFF + d) = srcH[idx];
                    *(uint4*)(smem + XP_BL_OFF + d) = srcL[idx];
                }
            }
            for (int idx = tid; idx < ROWS * KCH; idx += TPB) {
                int r = idx / KCH, k = idx - r * KCH;
                float v = x[(row0 + r) * NIN + kc * KCH + k];
                __half h = __float2half_rn(v);
                __half lo = __float2half_rn(v - __half2float(h));
                uint32_t d = (uint32_t)(r * XP_BSTR + k * 2);
                *(__half*)(smem + XP_AH_OFF + d) = h;
                *(__half*)(smem + XP_AL_OFF + d) = lo;
            }
            __syncthreads();

#pragma unroll
            for (int ks = 0; ks < 7; ++ks) {
                const uint32_t kb = (uint32_t)(ks * 32);
                uint32_t aH[2][4], aL[2][4], bH[2][4], bL[2][4];
#pragma unroll
                for (int mt = 0; mt < 2; ++mt) {
                    ldsm_x4(aAddrH + (uint32_t)(mt * 16 * XP_BSTR) + kb,
                            aH[mt][0], aH[mt][1], aH[mt][2], aH[mt][3]);
                    ldsm_x4(aAddrL + (uint32_t)(mt * 16 * XP_BSTR) + kb,
                            aL[mt][0], aL[mt][1], aL[mt][2], aL[mt][3]);
                }
#pragma unroll
                for (int np = 0; np < 2; ++np) {
                    ldsm_x4(bAddrH + (uint32_t)((colBase + np * 16) * XP_BSTR) + kb,
                            bH[np][0], bH[np][1], bH[np][2], bH[np][3]);
                    ldsm_x4(bAddrL + (uint32_t)((colBase + np * 16) * XP_BSTR) + kb,
                            bL[np][0], bL[np][1], bL[np][2], bL[np][3]);
                }
#pragma unroll
                for (int mt = 0; mt < 2; ++mt)
#pragma unroll
                    for (int nt = 0; nt < 4; ++nt) {
                        uint32_t* bh = &bH[nt >> 1][(nt & 1) * 2];
                        uint32_t* bl = &bL[nt >> 1][(nt & 1) * 2];
                        hmma(cR[mt][nt], aH[mt], bh);
                        hmma(cR[mt][nt], aH[mt], bl);
                        hmma(cR[mt][nt], aL[mt], bh);
                    }
            }
        }
        // += (b_ip + bq); s0 = c — all in registers, no gmem round-trip
#pragma unroll
        for (int nt = 0; nt < 4; ++nt) {
            int col = colBase + nt * 8 + c0;
            float a0 = g_add[col], a1 = g_add[col + 1];
#pragma unroll
            for (int mt = 0; mt < 2; ++mt)
#pragma unroll
                for (int ep = 0; ep < 2; ++ep) {
                    cR[mt][nt][ep * 2 + 0] += a0;
                    cR[mt][nt][ep * 2 + 1] += a1;
                }
        }
    }
    float s[2][4][4];
#pragma unroll
    for (int mt = 0; mt < 2; ++mt)
#pragma unroll
        for (int nt = 0; nt < 4; ++nt)
#pragma unroll
            for (int e = 0; e < 4; ++e) s[mt][nt][e] = cR[mt][nt][e];

    // ================= stage Wq into padded SMEM (after xproj reads done) =================
    __syncthreads();
    {
        const int4* src = (const int4*)g_Wq16;
        int4* dst = (int4*)smem;
        for (int i = tid; i < NH * 32; i += TPB) {
            int n = i >> 5, kk = i & 31;
            dst[n * 33 + kk] = src[i];
        }
    }
    const float alpha = g_ab[0];
    const float betaS = g_ab[1] * (1.0f / 255.0f);
    __syncthreads();

    const uint32_t aPieceI = (uint32_t)((l & 15) * WQ_STRIDE + (l & 16));
    const uint32_t aAddr0 = sbase + AS0_OFF + aPieceI;
    const uint32_t aAddr1 = sbase + AS1_OFF + aPieceI;
    const uint32_t bAddrN = sbase + (uint32_t)(((l & 7) + ((l & 16) >> 1)) * WQ_STRIDE + (l & 8) * 2);

    // ---- hoist Wq B-fragments for ksteps 0..7 (iteration-invariant) ----
    uint32_t bR[8][2][4];
#pragma unroll
    for (int ks = 0; ks < 8; ++ks)
#pragma unroll
        for (int np = 0; np < 2; ++np)
            ldsm_x4(bAddrN + (uint32_t)((colBase + np * 16) * WQ_STRIDE) + (uint32_t)(ks * 32),
                    bR[ks][np][0], bR[ks][np][1], bR[ks][np][2], bR[ks][np][3]);

    unsigned sticky = 0u;
    int done_it = MAXIT;

    // ================= PHASE 1: iterate until LOCAL convergence (2 syncs/iter) ===========
#pragma unroll 1
    for (int it = 0; it < MAXIT; ++it) {
        // 1. tanh(s) -> fp16 A tile (buf0)
#pragma unroll
        for (int mt = 0; mt < 2; ++mt)
#pragma unroll
            for (int nt = 0; nt < 4; ++nt)
#pragma unroll
                for (int ep = 0; ep < 2; ++ep) {
                    float t0 = tanh_f32(s[mt][nt][ep * 2 + 0]);
                    float t1 = tanh_f32(s[mt][nt][ep * 2 + 1]);
                    uint32_t pk;
                    asm("cvt.rn.f16x2.f32 %0, %1, %2;" : "=r"(pk) : "f"(t1), "f"(t0));
                    int row = mt * 16 + r0 + 8 * ep;
                    int col = colBase + nt * 8 + c0;
                    *(uint32_t*)(smem + AS0_OFF + row * WQ_STRIDE + col * 2) = pk;
                }
        __syncthreads();

        // 2. acc = tanh(s) @ Wq^T
        float acc[2][4][4];
#pragma unroll
        for (int mt = 0; mt < 2; ++mt)
#pragma unroll
            for (int nt = 0; nt < 4; ++nt)
#pragma unroll
                for (int e = 0; e < 4; ++e) acc[mt][nt][e] = 0.0f;
#pragma unroll
        for (int ks = 0; ks < 16; ++ks) {
            const uint32_t kb = (uint32_t)(ks * 32);
            uint32_t aF[2][4];
#pragma unroll
            for (int mt = 0; mt < 2; ++mt)
                ldsm_x4(aAddr0 + (uint32_t)(mt * 16 * WQ_STRIDE) + kb,
                        aF[mt][0], aF[mt][1], aF[mt][2], aF[mt][3]);
            uint32_t bT[2][4];
            if (ks < 8) {
#pragma unroll
                for (int np = 0; np < 2; ++np)
#pragma unroll
                    for (int e = 0; e < 4; ++e) bT[np][e] = bR[ks][np][e];
            } else {
#pragma unroll
                for (int np = 0; np < 2; ++np)
                    ldsm_x4(bAddrN + (uint32_t)((colBase + np * 16) * WQ_STRIDE) + kb,
                            bT[np][0], bT[np][1], bT[np][2], bT[np][3]);
            }
#pragma unroll
            for (int mt = 0; mt < 2; ++mt)
#pragma unroll
                for (int nt = 0; nt < 4; ++nt)
                    hmma(acc[mt][nt], aF[mt], &bT[nt >> 1][(nt & 1) * 2]);
        }

        // 3. update s + per-row slice inf-norm
        float dmax[4] = {0.0f, 0.0f, 0.0f, 0.0f};
#pragma unroll
        for (int mt = 0; mt < 2; ++mt)
#pragma unroll
            for (int nt = 0; nt < 4; ++nt)
#pragma unroll
                for (int e = 0; e < 4; ++e) {
                    float sv = s[mt][nt][e];
                    float sn = fmaf(alpha, sv, fmaf(betaS, acc[mt][nt][e], cR[mt][nt][e]));
                    int j = mt * 2 + (e >> 1);
                    dmax[j] = fmaxf(dmax[j], fabsf(sn - sv));
                    s[mt][nt][e] = sn;
                }
#pragma unroll
        for (int off = 1; off <= 2; off <<= 1)
#pragma unroll
            for (int j = 0; j < 4; ++j)
                dmax[j] = fmaxf(dmax[j], __shfl_xor_sync(0xFFFFFFFFu, dmax[j], off));
        if ((l & 3) == 0) {
#pragma unroll
            for (int j = 0; j < 4; ++j)
                sW[w * 32 + r0 + 8 * j] = dmax[j];
        }
        __syncthreads();

        // 4. redundant vote — every warp computes the identical ballot (no 3rd sync)
        float m = sW[l];
#pragma unroll
        for (int ww = 1; ww < 8; ++ww)
            m = fmaxf(m, sW[ww * 32 + l]);
        sticky |= __ballot_sync(0xFFFFFFFFu, m < TOLV);
        if (sticky == 0xFFFFFFFFu) { done_it = it + 1; break; }
    }

    // ================= single grid barrier: T = max(t_local) =================
    if (tid == 0) {
        atomicMax(&g_T, (unsigned)done_it);
        __threadfence();
        atomicAdd(&g_bar[0], 1u);
        unsigned vv;
        do {
            asm volatile("ld.acquire.gpu.u32 %0, [%1];" : "=r"(vv) : "l"(&g_bar[0]) : "memory");
        } while (vv < (unsigned)NCTA);
        unsigned tg;
        asm volatile("ld.acquire.gpu.u32 %0, [%1];" : "=r"(tg) : "l"(&g_T) : "memory");
        *sRem = tg;
    }
    __syncthreads();
    const int rem = (int)*sRem - done_it;

    // ================= PHASE 2: counted tail, 1 sync/iter (double-buffered A) ============
#pragma unroll 1
    for (int i = 0; i < rem; ++i) {
        const uint32_t abase = (i & 1) ? aAddr1 : aAddr0;
        const uint32_t sbuf = (i & 1) ? AS1_OFF : AS0_OFF;
#pragma unroll
        for (int mt = 0; mt < 2; ++mt)
#pragma unroll
            for (int nt = 0; nt < 4; ++nt)
#pragma unroll
                for (int ep = 0; ep < 2; ++ep) {
                    float t0 = tanh_f32(s[mt][nt][ep * 2 + 0]);
                    float t1 = tanh_f32(s[mt][nt][ep * 2 + 1]);
                    uint32_t pk;
                    asm("cvt.rn.f16x2.f32 %0, %1, %2;" : "=r"(pk) : "f"(t1), "f"(t0));
                    int row = mt * 16 + r0 + 8 * ep;
                    int col = colBase + nt * 8 + c0;
                    *(uint32_t*)(smem + sbuf + row * WQ_STRIDE + col * 2) = pk;
                }
        __syncthreads();

        float acc[2][4][4];
#pragma unroll
        for (int mt = 0; mt < 2; ++mt)
#pragma unroll
            for (int nt = 0; nt < 4; ++nt)
#pragma unroll
                for (int e = 0; e < 4; ++e) acc[mt][nt][e] = 0.0f;
#pragma unroll
        for (int ks = 0; ks < 16; ++ks) {
            const uint32_t kb = (uint32_t)(ks * 32);
            uint32_t aF[2][4];
#pragma unroll
            for (int mt = 0; mt < 2; ++mt)
                ldsm_x4(abase + (uint32_t)(mt * 16 * WQ_STRIDE) + kb,
                        aF[mt][0], aF[mt][1], aF[mt][2], aF[mt][3]);
            uint32_t bT[2][4];
            if (ks < 8) {
#pragma unroll
                for (int np = 0; np < 2; ++np)
#pragma unroll
                    for (int e = 0; e < 4; ++e) bT[np][e] = bR[ks][np][e];
            } else {
#pragma unroll
                for (int np = 0; np < 2; ++np)
                    ldsm_x4(bAddrN + (uint32_t)((colBase + np * 16) * WQ_STRIDE) + kb,
                            bT[np][0], bT[np][1], bT[np][2], bT[np][3]);
            }
#pragma unroll
            for (int mt = 0; mt < 2; ++mt)
#pragma unroll
                for (int nt = 0; nt < 4; ++nt)
                    hmma(acc[mt][nt], aF[mt], &bT[nt >> 1][(nt & 1) * 2]);
        }
#pragma unroll
        for (int mt = 0; mt < 2; ++mt)
#pragma unroll
            for (int nt = 0; nt < 4; ++nt)
#pragma unroll
                for (int e = 0; e < 4; ++e)
                    s[mt][nt][e] = fmaf(alpha, s[mt][nt][e],
                                        fmaf(betaS, acc[mt][nt][e], cR[mt][nt][e]));
    }

    // ================= epilogue: out = s @ Wop^T + bop =================
    __syncthreads();
    float* wopS = (float*)smem;
    float* partS = (float*)(smem + 10240);
    for (int i = tid; i < NOUT * NH; i += TPB) wopS[i] = Wop[i];
    __syncthreads();
    float part[4][NOUT];
#pragma unroll
    for (int j = 0; j < 4; ++j) {
#pragma unroll
        for (int o = 0; o < NOUT; ++o) part[j][o] = 0.0f;
        int mt = j >> 1, eb = (j & 1) * 2;
#pragma unroll
        for (int nt = 0; nt < 4; ++nt)
#pragma unroll
            for (int b = 0; b < 2; ++b) {
                float sv = s[mt][nt][eb + b];
                int col = colBase + nt * 8 + c0 + b;
#pragma unroll
                for (int o = 0; o < NOUT; ++o)
                    part[j][o] = fmaf(sv, wopS[o * NH + col], part[j][o]);
            }
    }
#pragma unroll
    for (int off = 1; off <= 2; off <<= 1)
#pragma unroll
        for (int j = 0; j < 4; ++j)
#pragma unroll
            for (int o = 0; o < NOUT; ++o)
                part[j][o] += __shfl_xor_sync(0xFFFFFFFFu, part[j][o], off);
    if ((l & 3) == 0) {
#pragma unroll
        for (int j = 0; j < 4; ++j)
#pragma unroll
            for (int o = 0; o < NOUT; ++o)
                partS[((r0 + 8 * j) * 8 + w) * NOUT + o] = part[j][o];
    }
    __syncthreads();
    for (int i = tid; i < ROWS * NOUT; i += TPB) {
        int row = i / NOUT, o = i % NOUT;
        float v = bop[o];
#pragma unroll
        for (int ww = 0; ww < 8; ++ww)
            v += partS[(row * 8 + ww) * NOUT + o];
        out[(row0 + row) * NOUT + o] = v;
    }
}

// ---------------- launch ----------------
extern "C" void kernel_launch(void* const* d_in, const int* in_sizes, int n_in,
                              void* d_out, int out_size) {
    const float *x = nullptr, *W_ip = nullptr, *b_ip = nullptr, *W_op = nullptr,
                *b_op = nullptr, *W_raw = nullptr, *b_raw = nullptr,
                *a_raw = nullptr, *be_raw = nullptr;
    for (int i = 0; i < n_in; ++i) {
        const float* p = (const float*)d_in[i];
        switch (in_sizes[i]) {
            case NB * NIN:  x = p; break;
            case NH * NIN:  W_ip = p; break;
            case NH * NH:   W_raw = p; break;
            case NOUT * NH: W_op = p; break;
            case NOUT:      b_op = p; break;
            case NH:        if (!b_ip) b_ip = p; else b_raw = p; break;
            case 1:         if (!a_raw) a_raw = p; else be_raw = p; break;
            default: break;
        }
    }

    cudaFuncSetAttribute(k_main, cudaFuncAttributeMaxDynamicSharedMemorySize, SMEM_SZ);

    k_setup<<<2 * NH + 1, 256>>>(W_raw, b_raw, a_raw, be_raw, b_ip, W_ip);
    k_main<<<NCTA, TPB, SMEM_SZ>>>(x, W_op, b_op, (float*)d_out);
}